// round 1
// baseline (speedup 1.0000x reference)
#include <cuda_runtime.h>

#define SQ   4096
#define BHN  64
#define PIT  68          // smem row pitch in floats (even, 272B -> float4-aligned rows)
#define NSPLIT 16

typedef unsigned long long u64t;

// ---------------- scratch (static device globals; no allocations) ----------------
__device__ float g_Qlm[BHN*64*64];            // raw landmark means of Q
__device__ float g_Klm[BHN*64*64];            // raw landmark means of K
__device__ float g_F  [BHN*64*64];            // softmax(Qlm K^T) @ V
__device__ float g_W  [BHN*64*64];            // inv(kernel_2) @ F
__device__ float g_pacc[(size_t)NSPLIT*BHN*64*64];   // split partial accumulators
__device__ float g_pmax[NSPLIT*BHN*64];
__device__ float g_psum[NSPLIT*BHN*64];

// ---------------- packed f32x2 helpers (Blackwell FFMA2 path) ----------------
__device__ __forceinline__ u64t pk2(float lo, float hi) {
    u64t r; asm("mov.b64 %0, {%1, %2};" : "=l"(r) : "f"(lo), "f"(hi)); return r;
}
__device__ __forceinline__ u64t ffma2(u64t a, u64t b, u64t c) {
    u64t d; asm("fma.rn.f32x2 %0, %1, %2, %3;" : "=l"(d) : "l"(a), "l"(b), "l"(c)); return d;
}
__device__ __forceinline__ u64t fmul2(u64t a, u64t b) {
    u64t d; asm("mul.rn.f32x2 %0, %1, %2;" : "=l"(d) : "l"(a), "l"(b)); return d;
}

// ---------------- 64x64x64 smem matmul core, 256 threads ----------------
// C[i][j] = sum_k A[i][k]*B[k][j], all pitch PIT.
// thread -> rows {rq, rq+16, rq+32, rq+48}, colpairs {2cq..2cq+1, 2cq+32..2cq+33}
__device__ __forceinline__ void mm64_core(const float* __restrict__ A,
                                          const float* __restrict__ B,
                                          int rq, int cq, u64t acc[4][2]) {
#pragma unroll
    for (int k = 0; k < 64; k++) {
        u64t b0 = *(const u64t*)(B + k*PIT + 2*cq);
        u64t b1 = *(const u64t*)(B + k*PIT + 2*cq + 32);
#pragma unroll
        for (int r = 0; r < 4; r++) {
            float a = A[(rq + 16*r)*PIT + k];
            u64t a2 = pk2(a, a);
            acc[r][0] = ffma2(a2, b0, acc[r][0]);
            acc[r][1] = ffma2(a2, b1, acc[r][1]);
        }
    }
}

__device__ __noinline__ void mm64_smem(const float* __restrict__ A,
                                       const float* __restrict__ B,
                                       float* __restrict__ C, int tid) {
    int cq = tid & 15, rq = tid >> 4;
    u64t acc[4][2] = {};
    mm64_core(A, B, rq, cq, acc);
#pragma unroll
    for (int r = 0; r < 4; r++) {
        *(u64t*)(C + (rq+16*r)*PIT + 2*cq)      = acc[r][0];
        *(u64t*)(C + (rq+16*r)*PIT + 2*cq + 32) = acc[r][1];
    }
}

// ---------------- K1: landmark pooling (unscaled means) ----------------
__global__ void __launch_bounds__(256) pool_kernel(const float* __restrict__ Q,
                                                   const float* __restrict__ K) {
    int bh = blockIdx.x >> 6, lm = blockIdx.x & 63;
    int d = threadIdx.x & 63, rg = threadIdx.x >> 6;
    const float* qb = Q + ((size_t)bh*SQ + lm*64)*64 + d;
    const float* kb = K + ((size_t)bh*SQ + lm*64)*64 + d;
    float sq = 0.f, sk = 0.f;
    for (int r = rg; r < 64; r += 4) { sq += qb[(size_t)r*64]; sk += kb[(size_t)r*64]; }
    __shared__ float shq[256], shk[256];
    shq[threadIdx.x] = sq; shk[threadIdx.x] = sk;
    __syncthreads();
    if (rg == 0) {
        float q = (shq[d] + shq[64+d] + shq[128+d] + shq[192+d]) * (1.0f/64.0f);
        float k = (shk[d] + shk[64+d] + shk[128+d] + shk[192+d]) * (1.0f/64.0f);
        g_Qlm[(bh*64 + lm)*64 + d] = q;
        g_Klm[(bh*64 + lm)*64 + d] = k;
    }
}

// ---------------- K2: F = softmax_S(0.125*Qlm K^T) @ V  (split over S) ----------------
__global__ void __launch_bounds__(256) kc_kernel(const float* __restrict__ K,
                                                 const float* __restrict__ V) {
    extern __shared__ float sm[];
    float* Qs  = sm;
    float* KtT = sm + 64*PIT;
    float* Vt  = sm + 2*64*PIT;
    float* L   = sm + 3*64*PIT;
    __shared__ float sred[256], rmax[64], rsum[64], rfac[64];
    int tid = threadIdx.x;
    int sp = blockIdx.x, bh = blockIdx.y;

    for (int idx = tid; idx < 4096; idx += 256) {
        int i = idx >> 6, k = idx & 63;
        Qs[i*PIT + k] = g_Qlm[bh*4096 + idx] * 0.125f;   // fold scale^2 into Qlm
    }
    if (tid < 64) { rmax[tid] = -1e30f; rsum[tid] = 0.0f; }
    u64t acc[4][2] = {};
    int cq = tid & 15, rq = tid >> 4;
    int q = tid & 3,  r  = tid >> 2;
    __syncthreads();

#pragma unroll 1
    for (int t = 0; t < 4; t++) {
        int s0 = sp*256 + t*64;
#pragma unroll
        for (int itld = 0; itld < 4; itld++) {
            int f4 = tid + itld*256;
            int j = f4 >> 4, k4 = (f4 & 15) << 2;
            float4 kv = *(const float4*)(K + ((size_t)bh*SQ + s0 + j)*64 + k4);
            KtT[(k4+0)*PIT + j] = kv.x; KtT[(k4+1)*PIT + j] = kv.y;
            KtT[(k4+2)*PIT + j] = kv.z; KtT[(k4+3)*PIT + j] = kv.w;
            float4 vv = *(const float4*)(V + ((size_t)bh*SQ + s0 + j)*64 + k4);
            *(float4*)(Vt + j*PIT + k4) = vv;
        }
        __syncthreads();
        mm64_smem(Qs, KtT, L, tid);           // L[i][j] = logits for this tile
        __syncthreads();
        // ---- online softmax update (4 threads per row) ----
        float* Lr = L + r*PIT + q*16;
        float mt = Lr[0];
#pragma unroll
        for (int c = 1; c < 16; c++) mt = fmaxf(mt, Lr[c]);
        sred[tid] = mt; __syncthreads();
        if (q == 0) {
            float m4 = fmaxf(fmaxf(sred[tid], sred[tid+1]), fmaxf(sred[tid+2], sred[tid+3]));
            float nm = fmaxf(rmax[r], m4);
            rfac[r] = __expf(rmax[r] - nm);
            rmax[r] = nm;
        }
        __syncthreads();
        float nm = rmax[r], ps = 0.f;
#pragma unroll
        for (int c = 0; c < 16; c++) { float e = __expf(Lr[c] - nm); Lr[c] = e; ps += e; }
        __syncthreads();
        sred[tid] = ps; __syncthreads();
        if (q == 0) rsum[r] = rsum[r]*rfac[r] + sred[tid]+sred[tid+1]+sred[tid+2]+sred[tid+3];
        __syncthreads();
        // rescale existing accumulator rows, then acc += P * Vt
#pragma unroll
        for (int rr = 0; rr < 4; rr++) {
            float f = rfac[rq + 16*rr];
            u64t f2 = pk2(f, f);
            acc[rr][0] = fmul2(acc[rr][0], f2);
            acc[rr][1] = fmul2(acc[rr][1], f2);
        }
        mm64_core(L, Vt, rq, cq, acc);
        __syncthreads();
    }
    size_t base = ((size_t)sp*BHN + bh)*4096;
#pragma unroll
    for (int rr = 0; rr < 4; rr++) {
        *(u64t*)(g_pacc + base + (rq+16*rr)*64 + 2*cq)      = acc[rr][0];
        *(u64t*)(g_pacc + base + (rq+16*rr)*64 + 2*cq + 32) = acc[rr][1];
    }
    if (tid < 64) {
        g_pmax[(sp*BHN+bh)*64 + tid] = rmax[tid];
        g_psum[(sp*BHN+bh)*64 + tid] = rsum[tid];
    }
}

// ---------------- K3: combine split partials -> g_F ----------------
__global__ void __launch_bounds__(256) kc_reduce() {
    int bh = blockIdx.x, tid = threadIdx.x;
    int d = tid & 63, ig = tid >> 6;
    for (int i = ig; i < 64; i += 4) {
        float gm = -1e30f;
#pragma unroll
        for (int s = 0; s < NSPLIT; s++) gm = fmaxf(gm, g_pmax[(s*BHN+bh)*64 + i]);
        float tot = 0.f, w[NSPLIT];
#pragma unroll
        for (int s = 0; s < NSPLIT; s++) {
            w[s] = __expf(g_pmax[(s*BHN+bh)*64 + i] - gm);
            tot += g_psum[(s*BHN+bh)*64 + i] * w[s];
        }
        float v = 0.f;
#pragma unroll
        for (int s = 0; s < NSPLIT; s++)
            v += g_pacc[((size_t)s*BHN+bh)*4096 + i*64 + d] * w[s];
        g_F[bh*4096 + i*64 + d] = v / tot;
    }
}

// ---------------- K4: kernel_2 softmax + Newton-Schulz inverse + W = inv@F ----------------
__global__ void __launch_bounds__(256) newton_kernel() {
    extern __shared__ float sm[];
    float* A  = sm;
    float* Vb = sm + 1*64*PIT;
    float* P  = sm + 2*64*PIT;
    float* T  = sm + 3*64*PIT;
    float* U  = sm + 4*64*PIT;
    __shared__ float sred[256], srow[64], scol[64], sscale[1];
    int tid = threadIdx.x, bh = blockIdx.x;

    for (int idx = tid; idx < 4096; idx += 256) {
        int i = idx >> 6, k = idx & 63;
        T[i*PIT + k] = g_Qlm[bh*4096 + idx] * 0.125f;   // scaled Qlm
        U[k*PIT + i] = g_Klm[bh*4096 + idx];            // Klm transposed (k-major)
    }
    __syncthreads();
    mm64_smem(T, U, A, tid);          // A = 0.125 * Qlm Klm^T
    __syncthreads();
    // full softmax of A rows
    {
        int q = tid & 3, r = tid >> 2;
        float* Lr = A + r*PIT + q*16;
        float mt = Lr[0];
#pragma unroll
        for (int c = 1; c < 16; c++) mt = fmaxf(mt, Lr[c]);
        sred[tid] = mt; __syncthreads();
        float m = fmaxf(fmaxf(sred[r*4], sred[r*4+1]), fmaxf(sred[r*4+2], sred[r*4+3]));
        float ps = 0.f;
#pragma unroll
        for (int c = 0; c < 16; c++) { float e = __expf(Lr[c] - m); Lr[c] = e; ps += e; }
        __syncthreads();
        sred[tid] = ps; __syncthreads();
        float s = sred[r*4] + sred[r*4+1] + sred[r*4+2] + sred[r*4+3];
        float inv = 1.0f / s;
#pragma unroll
        for (int c = 0; c < 16; c++) Lr[c] *= inv;
    }
    __syncthreads();
    // scale = 1 / (max row sum * max col sum)   (all entries positive)
    if (tid < 64)       { float s = 0.f; for (int j = 0; j < 64; j++) s += A[tid*PIT + j]; srow[tid] = s; }
    else if (tid < 128) { int c = tid - 64; float s = 0.f; for (int i = 0; i < 64; i++) s += A[i*PIT + c]; scol[c] = s; }
    __syncthreads();
    if (tid == 0) {
        float mr = srow[0], mc = scol[0];
        for (int i = 1; i < 64; i++) { mr = fmaxf(mr, srow[i]); mc = fmaxf(mc, scol[i]); }
        sscale[0] = 1.0f / (mr * mc);
    }
    __syncthreads();
    float sc = sscale[0];
    for (int idx = tid; idx < 4096; idx += 256) {
        int i = idx >> 6, j = idx & 63;
        Vb[j*PIT + i] = A[i*PIT + j] * sc;             // V0 = scale * A^T
    }
    __syncthreads();
#pragma unroll 1
    for (int it = 0; it < 6; it++) {
        mm64_smem(A, Vb, P, tid); __syncthreads();      // P = K V
        for (int idx = tid; idx < 4096; idx += 256) {
            int i = idx >> 6, j = idx & 63;
            T[i*PIT + j] = (i == j ? 7.0f : 0.0f) - P[i*PIT + j];
        }
        __syncthreads();
        mm64_smem(P, T, U, tid); __syncthreads();       // U = KV(7I - KV)
        for (int idx = tid; idx < 4096; idx += 256) {
            int i = idx >> 6, j = idx & 63;
            T[i*PIT + j] = (i == j ? 15.0f : 0.0f) - U[i*PIT + j];
        }
        __syncthreads();
        mm64_smem(P, T, U, tid); __syncthreads();       // U = KV(15I - ...)
        for (int idx = tid; idx < 4096; idx += 256) {
            int i = idx >> 6, j = idx & 63;
            T[i*PIT + j] = (i == j ? 3.25f : 0.0f) - 0.25f * U[i*PIT + j];  // 0.25*(13I - U)
        }
        __syncthreads();
        mm64_smem(Vb, T, U, tid); __syncthreads();      // V_new = V * T
        float* tmp = Vb; Vb = U; U = tmp;
    }
    // W = inv @ F
    for (int idx = tid; idx < 4096; idx += 256) {
        int j = idx >> 6, d = idx & 63;
        T[j*PIT + d] = g_F[bh*4096 + idx];
    }
    __syncthreads();
    mm64_smem(Vb, T, P, tid);
    __syncthreads();
    for (int idx = tid; idx < 4096; idx += 256) {
        int i = idx >> 6, d = idx & 63;
        g_W[bh*4096 + idx] = P[i*PIT + d];
    }
}

// ---------------- K5: X = softmax_m(0.125*Q Klm^T) @ W ----------------
__global__ void __launch_bounds__(256) kd_kernel(const float* __restrict__ Q,
                                                 float* __restrict__ X) {
    extern __shared__ float sm[];
    float* Ws  = sm;
    float* KlT = sm + 64*PIT;
    float* Qt  = sm + 2*64*PIT;
    float* L   = sm + 3*64*PIT;
    __shared__ float sred[256], rinv[64];
    int tid = threadIdx.x;
    int ch = blockIdx.x, bh = blockIdx.y;

    for (int idx = tid; idx < 4096; idx += 256) {
        int i = idx >> 6, k = idx & 63;
        Ws[i*PIT + k]  = g_W[bh*4096 + idx];
        KlT[k*PIT + i] = g_Klm[bh*4096 + idx];          // transposed
    }
    int cq = tid & 15, rq = tid >> 4;
    int q = tid & 3,  r  = tid >> 2;
    __syncthreads();

#pragma unroll 1
    for (int t = 0; t < 4; t++) {
        int s0 = ch*256 + t*64;
#pragma unroll
        for (int itld = 0; itld < 4; itld++) {
            int f4 = tid + itld*256;
            int j = f4 >> 4, k4 = (f4 & 15) << 2;
            float4 qv = *(const float4*)(Q + ((size_t)bh*SQ + s0 + j)*64 + k4);
            qv.x *= 0.125f; qv.y *= 0.125f; qv.z *= 0.125f; qv.w *= 0.125f;
            *(float4*)(Qt + j*PIT + k4) = qv;
        }
        __syncthreads();
        mm64_smem(Qt, KlT, L, tid);                     // logits [64 tok][64 lm]
        __syncthreads();
        float* Lr = L + r*PIT + q*16;
        float mt = Lr[0];
#pragma unroll
        for (int c = 1; c < 16; c++) mt = fmaxf(mt, Lr[c]);
        sred[tid] = mt; __syncthreads();
        float m = fmaxf(fmaxf(sred[r*4], sred[r*4+1]), fmaxf(sred[r*4+2], sred[r*4+3]));
        float ps = 0.f;
#pragma unroll
        for (int c = 0; c < 16; c++) { float e = __expf(Lr[c] - m); Lr[c] = e; ps += e; }
        __syncthreads();
        sred[tid] = ps; __syncthreads();
        if (q == 0) rinv[r] = 1.0f / (sred[tid]+sred[tid+1]+sred[tid+2]+sred[tid+3]);
        __syncthreads();
        u64t acc[4][2] = {};
        mm64_core(L, Ws, rq, cq, acc);                  // unnormalized P~ @ W
#pragma unroll
        for (int rr = 0; rr < 4; rr++) {
            float f = rinv[rq + 16*rr];
            u64t f2 = pk2(f, f);
            size_t ob = ((size_t)bh*SQ + s0 + rq + 16*rr)*64;
            *(u64t*)(X + ob + 2*cq)      = fmul2(acc[rr][0], f2);
            *(u64t*)(X + ob + 2*cq + 32) = fmul2(acc[rr][1], f2);
        }
        __syncthreads();
    }
}

// ---------------- launcher ----------------
extern "C" void kernel_launch(void* const* d_in, const int* in_sizes, int n_in,
                              void* d_out, int out_size) {
    (void)in_sizes; (void)n_in; (void)out_size;
    const float* Q = (const float*)d_in[0];
    const float* K = (const float*)d_in[1];
    const float* V = (const float*)d_in[2];
    float* X = (float*)d_out;

    const int SMEM_MM     = 4*64*PIT*4;   // 69632 B
    const int SMEM_NEWTON = 5*64*PIT*4;   // 87040 B
    cudaFuncSetAttribute(kc_kernel,     cudaFuncAttributeMaxDynamicSharedMemorySize, SMEM_MM);
    cudaFuncSetAttribute(kd_kernel,     cudaFuncAttributeMaxDynamicSharedMemorySize, SMEM_MM);
    cudaFuncSetAttribute(newton_kernel, cudaFuncAttributeMaxDynamicSharedMemorySize, SMEM_NEWTON);

    pool_kernel<<<BHN*64, 256>>>(Q, K);
    kc_kernel<<<dim3(NSPLIT, BHN), 256, SMEM_MM>>>(K, V);
    kc_reduce<<<BHN, 256>>>();
    newton_kernel<<<BHN, 256, SMEM_NEWTON>>>();
    kd_kernel<<<dim3(16, BHN), 256, SMEM_MM>>>(Q, X);
}